// round 9
// baseline (speedup 1.0000x reference)
#include <cuda_runtime.h>
#include <cstdint>

#define IN_SIZE  256
#define N_NODES  1024
#define DEG      32
#define BATCH    16384
#define OUT_SIZE 16

#define BT      32                      // batch columns per CTA (= warp width)
#define NTHR    512                     // 16 warps
#define NWARP   16
#define NROWS   (IN_SIZE + N_NODES)     // 1280
#define NCTA    (BATCH / BT)            // 512
#define REC     17                      // uint4 per node record (16 pair-chunks + meta)
#define PB_NODES 64                     // max nodes per level chunk
#define PB_U4   (PB_NODES * REC)        // 1088 uint4 per buffer
#define AS_FLOATS (NROWS * BT)          // 40960 (row stride 32 words = 128 B)
#define MAXB    1100                    // max level-chunk boundaries
#define SMEM_BYTES (AS_FLOATS * 4 + 2 * PB_U4 * 16 + (MAXB + 4) * 4)

// ---------------- device globals ----------------
__device__ int   g_sched[N_NODES];      // slot -> node id (level-grouped)
__device__ int   g_nlvl;                // number of level chunks
__device__ int   g_lvloff[MAXB];        // chunk boundaries B[0..nlvl]
__device__ uint4 g_prec[N_NODES * REC]; // slot-major node records

// ---------------- prepass A: depth + level schedule (1 block) ----------------
__device__ __forceinline__ int redmax32(int v) {
    int r;
    asm("redux.sync.max.s32 %0, %1, 0xffffffff;" : "=r"(r) : "r"(v));
    return r;
}

#define PA_SMEM ((32768 + 1280 + 1025 + 1025 + 2) * 4)

__global__ void schedule_kernel(const int* __restrict__ idx) {
    extern __shared__ int sm[];
    int* s_idx = sm;                    // [1024*32]
    int* s_dep = sm + 32768;            // [1280] depth per activation row
    int* s_cnt = s_dep + 1280;          // [1025] level histogram
    int* s_off = s_cnt + 1025;          // [1025] level start slot (placement cursor)
    int* s_aux = s_off + 1025;          // [2]: maxd
    const int tid = threadIdx.x;

    {   // stage idx; init
        const int4* src = (const int4*)idx;
        int4* dst = (int4*)s_idx;
        for (int i = tid; i < 8192; i += 256) dst[i] = src[i];
        for (int i = tid; i < 256;  i += 256) s_dep[i] = 0;
        for (int i = tid; i < 1025; i += 256) s_cnt[i] = 0;
        if (tid == 0) s_aux[0] = 0;
    }
    __syncthreads();

    // ---- sequential depth, 8-node speculative window (warp 0) ----
    if (tid < 32) {
        const int lane = tid;
        for (int base = 0; base < N_NODES; base += 8) {
            const int lim = IN_SIZE + base;
            int r[8], m[8], d[8];
            #pragma unroll
            for (int j = 0; j < 8; j++) r[j] = s_idx[(base + j) * 32 + lane];
            #pragma unroll
            for (int j = 0; j < 8; j++) {
                int v = (r[j] < lim) ? s_dep[r[j]] : 0;   // in-window refs patched below
                m[j] = redmax32(v);
            }
            d[0] = m[0] + 1;
            #pragma unroll
            for (int j = 1; j < 8; j++) {
                int mm = m[j];
                #pragma unroll
                for (int k = 0; k < j; k++) {
                    if (__any_sync(0xffffffffu, r[j] == lim + k)) mm = max(mm, d[k]);
                }
                d[j] = mm + 1;
            }
            if (lane == 0) {
                #pragma unroll
                for (int j = 0; j < 8; j++) s_dep[lim + j] = d[j];
            }
            __syncwarp();   // order lane0's STS before next window's cross-lane LDS
        }
    }
    __syncthreads();

    // ---- level histogram + max level ----
    for (int i = tid; i < N_NODES; i += 256) {
        int l = s_dep[IN_SIZE + i];
        atomicAdd(&s_cnt[l], 1);
        atomicMax(&s_aux[0], l);
    }
    __syncthreads();

    // ---- level starts + chunked boundaries (<= PB_NODES per chunk) ----
    if (tid == 0) {
        int acc = 0, nb = 0, md = s_aux[0];
        g_lvloff[0] = 0;
        for (int l = 1; l <= md; l++) {
            s_off[l] = acc;
            int c = s_cnt[l];
            while (c > 0) {
                int take = (c < PB_NODES) ? c : PB_NODES;
                acc += take;  c -= take;
                g_lvloff[++nb] = acc;
            }
        }
        g_nlvl = nb;
    }
    __syncthreads();

    // ---- stable placement (warp 0, match_any) ----
    if (tid < 32) {
        const int lane = tid;
        for (int c = 0; c < 32; c++) {
            int i = c * 32 + lane;
            int l = s_dep[IN_SIZE + i];
            unsigned mask = __match_any_sync(0xffffffffu, l);
            int rank = __popc(mask & ((1u << lane) - 1u));
            int base_ = s_off[l];
            g_sched[base_ + rank] = i;
            if ((int)(__ffs(mask) - 1) == lane) s_off[l] = base_ + __popc(mask);
            __syncwarp();
        }
    }
}

// ---------------- prepass B: pack slot-major node records ----------------
// record[s]: j<16 -> { idx(2j)<<7, w(2j), idx(2j+1)<<7, w(2j+1) };  j==16 -> { storeoff,0,0,0 }
__global__ void pack3(const int* __restrict__ idx, const float* __restrict__ w) {
    int e = blockIdx.x * blockDim.x + threadIdx.x;
    if (e >= N_NODES * REC) return;
    int s = e / REC, j = e - s * REC;
    int node = g_sched[s];
    if (j < 16) {
        int d0 = 2 * j;
        g_prec[e] = make_uint4((unsigned)idx[node * DEG + d0]     << 7,
                               __float_as_uint(w[node * DEG + d0]),
                               (unsigned)idx[node * DEG + d0 + 1] << 7,
                               __float_as_uint(w[node * DEG + d0 + 1]));
    } else {
        g_prec[e] = make_uint4((unsigned)(IN_SIZE + node) << 7, 0u, 0u, 0u);
    }
}

// Exact tanh(x) = 1 - 2/(exp(2x)+1); ~1e-6 abs err, saturates correctly.
__device__ __forceinline__ float ftanh(float x) {
    float e = __expf(2.0f * x);
    return 1.0f - __fdividef(2.0f, e + 1.0f);
}

__device__ __forceinline__ void cp16(unsigned dst_smem, const void* src) {
    asm volatile("cp.async.cg.shared.global [%0], [%1], 16;"
                 :: "r"(dst_smem), "l"(src) : "memory");
}
__device__ __forceinline__ void cp_commit() { asm volatile("cp.async.commit_group;" ::: "memory"); }
__device__ __forceinline__ void cp_wait0()  { asm volatile("cp.async.wait_group 0;" ::: "memory"); }

extern __shared__ float SM[];

__global__ void __launch_bounds__(NTHR, 1)
ne_kernel(const float* __restrict__ x, float* __restrict__ out) {
    const int tid  = threadIdx.x;
    const int lane = tid & 31;
    const int wid  = tid >> 5;
    const int b0   = blockIdx.x * BT;

    float* As   = SM;                                   // [1280][32] floats, row = 128 B
    uint4* pbuf = (uint4*)(SM + AS_FLOATS);             // 2 x PB_U4
    int*   s_lv = (int*)(pbuf + 2 * PB_U4);             // boundaries
    const unsigned pbuf_u32 = (unsigned)__cvta_generic_to_shared(pbuf);

    const int nb = g_nlvl;

    // ---- stage inputs transposed: As[row][col] = x[b0+col][row]; cache boundaries ----
    {
        int bl = tid >> 4;          // 0..31
        int ts = tid & 15;
        const float4* xr = (const float4*)(x + (size_t)(b0 + bl) * IN_SIZE);
        #pragma unroll
        for (int k = ts; k < IN_SIZE / 4; k += 16) {
            float4 v = xr[k];
            int i = k * 4;
            As[(i + 0) * BT + bl] = v.x;
            As[(i + 1) * BT + bl] = v.y;
            As[(i + 2) * BT + bl] = v.z;
            As[(i + 3) * BT + bl] = v.w;
        }
        for (int i = tid; i <= nb; i += NTHR) s_lv[i] = g_lvloff[i];
    }
    __syncthreads();

    char* Acb = (char*)As + (lane << 2);    // this lane's column base

    // ---- prologue: stage chunk 0 into buffer 0 ----
    {
        int s0 = s_lv[0], s1 = s_lv[1];
        int n16 = (s1 - s0) * REC;
        for (int i = tid; i < n16; i += NTHR)
            cp16(pbuf_u32 + i * 16, g_prec + s0 * REC + i);
        cp_commit(); cp_wait0();
    }
    __syncthreads();

    // ---- level-chunk loop ----
    for (int k = 0; k < nb; k++) {
        // stage next chunk into the other buffer (overlapped with compute)
        if (k + 1 < nb) {
            int t0 = s_lv[k + 1], t1 = s_lv[k + 2];
            int n16 = (t1 - t0) * REC;
            unsigned dst = pbuf_u32 + ((k + 1) & 1) * (PB_U4 * 16);
            for (int i = tid; i < n16; i += NTHR)
                cp16(dst + i * 16, g_prec + t0 * REC + i);
        }
        cp_commit();

        // compute this chunk: one warp per node, lane = column
        int s0 = s_lv[k], s1 = s_lv[k + 1];
        const uint4* rec = pbuf + (k & 1) * PB_U4;
        for (int sl = s0 + wid; sl < s1; sl += NWARP) {
            const uint4* P = rec + (sl - s0) * REC;
            // hoist the whole record into registers (independent LDS.128 burst)
            uint4 R[16];
            #pragma unroll
            for (int j = 0; j < 16; j++) R[j] = P[j];
            unsigned so = P[16].x;                      // uniform store offset

            float a[8];
            #pragma unroll
            for (int i = 0; i < 8; i++) a[i] = 0.f;
            #pragma unroll
            for (int j = 0; j < 16; j++) {
                uint4 p = R[j];
                float v0 = *(const float*)(Acb + p.x);
                float v1 = *(const float*)(Acb + p.z);
                a[(2 * j)     & 7] = __fmaf_rn(__uint_as_float(p.y), v0, a[(2 * j)     & 7]);
                a[(2 * j + 1) & 7] = __fmaf_rn(__uint_as_float(p.w), v1, a[(2 * j + 1) & 7]);
            }
            float s01 = a[0] + a[1], s23 = a[2] + a[3];
            float s45 = a[4] + a[5], s67 = a[6] + a[7];
            float t = ftanh((s01 + s23) + (s45 + s67));
            *(float*)((char*)As + so + (lane << 2)) = t;    // conflict-free row store
        }

        cp_wait0();
        __syncthreads();
    }

    // ---- emit last OUT_SIZE node rows (by original id): out[o][b0+c] ----
    for (int e = tid; e < OUT_SIZE * BT; e += NTHR) {
        int o = e >> 5, c = e & 31;
        float v = As[(IN_SIZE + N_NODES - OUT_SIZE + o) * BT + c];
        out[(size_t)o * BATCH + b0 + c] = v;
    }
}

extern "C" void kernel_launch(void* const* d_in, const int* in_sizes, int n_in,
                              void* d_out, int out_size) {
    const float* x   = (const float*)d_in[0];   // [16384, 256] f32
    const float* w   = (const float*)d_in[1];   // [1024, 32]   f32
    const int*   idx = (const int*)  d_in[2];   // [1024, 32]   i32
    float*       out = (float*)d_out;           // [16, 16384]  f32

    cudaFuncSetAttribute(schedule_kernel, cudaFuncAttributeMaxDynamicSharedMemorySize, PA_SMEM);
    cudaFuncSetAttribute(ne_kernel, cudaFuncAttributeMaxDynamicSharedMemorySize, SMEM_BYTES);

    schedule_kernel<<<1, 256, PA_SMEM>>>(idx);
    pack3<<<(N_NODES * REC + 255) / 256, 256>>>(idx, w);
    ne_kernel<<<NCTA, NTHR, SMEM_BYTES>>>(x, out);
}